// round 13
// baseline (speedup 1.0000x reference)
#include <cuda_runtime.h>
#include <cuda_fp16.h>
#include <cstdint>
#include <math.h>

#define B    8
#define C    512
#define HW   1024
#define G    32
#define CPG  16
#define HEADS 8
#define DH   64
#define EPS  1e-5f
#define QSCALE 0.1803368867f   // 0.125 * log2(e)

// ---------------- scratch (device globals) ----------------------------------
__device__ float2 g_stats[B * G];

__device__ __half g_WhQ[3 * C * C];
__device__ __half g_WhP[C * C];
__device__ __half g_XTh [B * HW * C];          // [b][n][c]
__device__ __half g_AOTh[B * HW * C];          // [b][i][c]
__device__ __half g_qTh [B * HEADS * HW * DH]; // [bh][i][d] (log2-scaled)
__device__ __half g_kTh [B * HEADS * HW * DH]; // [bh][j][d]
__device__ __half g_Vh  [B * HEADS * DH * HW]; // [bh][d][j]

// =================== helpers ==================================================
__device__ __forceinline__ uint32_t smem_u32(const void* p) {
    uint32_t r;
    asm("{ .reg .u64 t; cvta.to.shared.u64 t, %1; cvt.u32.u64 %0, t; }"
        : "=r"(r) : "l"(p));
    return r;
}
#define CP_ASYNC16(dst, src) \
    asm volatile("cp.async.cg.shared.global [%0], [%1], 16;" :: "r"(dst), "l"(src) : "memory")
#define CP_COMMIT() asm volatile("cp.async.commit_group;" ::: "memory")
#define CP_WAIT2()  asm volatile("cp.async.wait_group 2;" ::: "memory")
#define CP_WAIT1()  asm volatile("cp.async.wait_group 1;" ::: "memory")
#define CP_WAIT0()  asm volatile("cp.async.wait_group 0;" ::: "memory")
#define BAR_GROUP(id) asm volatile("bar.sync %0, %1;" :: "r"(id), "r"(128) : "memory")

#define LDSM_X4(r, addr) \
    asm volatile("ldmatrix.sync.aligned.m8n8.x4.shared.b16 {%0,%1,%2,%3}, [%4];" \
        : "=r"((r)[0]), "=r"((r)[1]), "=r"((r)[2]), "=r"((r)[3]) : "r"(addr))
#define LDSM_X2(r, addr) \
    asm volatile("ldmatrix.sync.aligned.m8n8.x2.shared.b16 {%0,%1}, [%2];" \
        : "=r"((r)[0]), "=r"((r)[1]) : "r"(addr))

__device__ __forceinline__ void mma_f16(float* c, const uint32_t* a, const uint32_t* b) {
    asm volatile(
        "mma.sync.aligned.m16n8k16.row.col.f32.f16.f16.f32 "
        "{%0,%1,%2,%3}, {%4,%5,%6,%7}, {%8,%9}, {%0,%1,%2,%3};"
        : "+f"(c[0]), "+f"(c[1]), "+f"(c[2]), "+f"(c[3])
        : "r"(a[0]), "r"(a[1]), "r"(a[2]), "r"(a[3]), "r"(b[0]), "r"(b[1]));
}
// f16-accumulate MMA: D,C packed half2 (2 regs)
__device__ __forceinline__ void mma_h16(uint32_t* c, const uint32_t* a, const uint32_t* b) {
    asm volatile(
        "mma.sync.aligned.m16n8k16.row.col.f16.f16.f16.f16 "
        "{%0,%1}, {%2,%3,%4,%5}, {%6,%7}, {%0,%1};"
        : "+r"(c[0]), "+r"(c[1])
        : "r"(a[0]), "r"(a[1]), "r"(a[2]), "r"(a[3]), "r"(b[0]), "r"(b[1]));
}
__device__ __forceinline__ uint32_t packh(float x, float y) {
    __half2 h = __floats2half2_rn(x, y);
    return *(uint32_t*)&h;
}
__device__ __forceinline__ float ex2f(float x) {
    float y;
    asm("ex2.approx.f32 %0, %1;" : "=f"(y) : "f"(x));
    return y;
}
__device__ __forceinline__ uint32_t ex2h2(uint32_t x) {
    uint32_t y;
    asm("ex2.approx.f16x2 %0, %1;" : "=r"(y) : "r"(x));
    return y;
}
__device__ __forceinline__ uint32_t hmax2u(uint32_t a, uint32_t b) {
    __half2 r = __hmax2(*(__half2*)&a, *(__half2*)&b);
    return *(uint32_t*)&r;
}
__device__ __forceinline__ uint32_t hmul2u(uint32_t a, uint32_t b) {
    __half2 r = __hmul2(*(__half2*)&a, *(__half2*)&b);
    return *(uint32_t*)&r;
}
__device__ __forceinline__ uint32_t hsub2u(uint32_t a, uint32_t b) {
    __half2 r = __hsub2(*(__half2*)&a, *(__half2*)&b);
    return *(uint32_t*)&r;
}

// =========== fused prologue: gn stats + both weight converts ==================
__global__ __launch_bounds__(256) void prep_kernel(const float* __restrict__ x,
                                                   const float* __restrict__ qkv_w,
                                                   const float* __restrict__ proj_w) {
    int blk = blockIdx.x;
    if (blk < 256) {
        const float4* xp = (const float4*)(x + (size_t)blk * CPG * HW);
        const int N4 = CPG * HW / 4;
        float s = 0.f, s2 = 0.f;
        for (int i = threadIdx.x; i < N4; i += 256) {
            float4 v = xp[i];
            s  += v.x + v.y + v.z + v.w;
            s2 += v.x * v.x + v.y * v.y + v.z * v.z + v.w * v.w;
        }
        __shared__ float sh1[8], sh2[8];
        int lane = threadIdx.x & 31, wid = threadIdx.x >> 5;
        for (int o = 16; o; o >>= 1) {
            s  += __shfl_down_sync(0xffffffffu, s,  o);
            s2 += __shfl_down_sync(0xffffffffu, s2, o);
        }
        if (lane == 0) { sh1[wid] = s; sh2[wid] = s2; }
        __syncthreads();
        if (threadIdx.x == 0) {
            for (int i = 1; i < 8; i++) { sh1[0] += sh1[i]; sh2[0] += sh2[i]; }
            const float N = CPG * HW;
            float mean = sh1[0] * (1.f / N);
            float var  = sh2[0] * (1.f / N) - mean * mean;
            g_stats[blk] = make_float2(mean, rsqrtf(var + EPS));
        }
    } else if (blk < 1024) {
        int i = (blk - 256) * 1024 + threadIdx.x * 4;
        float4 v = *(const float4*)&qkv_w[i];
        *(uint32_t*)&g_WhQ[i]     = packh(v.x, v.y);
        *(uint32_t*)&g_WhQ[i + 2] = packh(v.z, v.w);
    } else {
        int i = (blk - 1024) * 1024 + threadIdx.x * 4;
        float4 v = *(const float4*)&proj_w[i];
        *(uint32_t*)&g_WhP[i]     = packh(v.x, v.y);
        *(uint32_t*)&g_WhP[i + 2] = packh(v.z, v.w);
    }
}

// ===== fused GN-apply + transpose + convert ===================================
__global__ __launch_bounds__(256) void convT_kernel(const float* __restrict__ x,
                                                    const float* __restrict__ gw,
                                                    const float* __restrict__ gb) {
    __shared__ float t[32][33];
    int n0 = blockIdx.x * 32, c0 = blockIdx.y * 32, b = blockIdx.z;
    const float* ip = x + (size_t)b * C * HW;
    int tx = threadIdx.x, ty = threadIdx.y;
#pragma unroll
    for (int k = 0; k < 4; k++) {
        int ch = c0 + ty + k * 8;
        float2 st = g_stats[b * G + (ch >> 4)];
        float v = ip[(size_t)ch * HW + n0 + tx];
        t[ty + k * 8][tx] = (v - st.x) * st.y * gw[ch] + gb[ch];
    }
    __syncthreads();
#pragma unroll
    for (int k = 0; k < 4; k++) {
        int ni = ty + k * 8;
        size_t o = (size_t)b * HW * C + (size_t)(n0 + ni) * C + c0 + tx;
        g_XTh[o] = __float2half(t[tx][ni]);
    }
}

// =================== dense GEMM config (4-stage, 2 CTA/SM) ====================
#define KC    32
#define ROWB  80
#define DTILE (128 * ROWB)
#define DSTG  (2 * DTILE)
#define SMQKV 81920
#define SMPROJ 81920

// =================== QKV GEMM (f16-acc MMA, fp32 promote every 2 chunks) ======
__global__ __launch_bounds__(256, 2) void qkv_gemm(const float* __restrict__ bias) {
    constexpr int BM = 128;
    extern __shared__ char smem[];

    const int tid = threadIdx.x;
    const int lane = tid & 31, wid = tid >> 5;
    const int wm = wid & 1, wn = wid >> 1;
    const int n0 = blockIdx.x * 128, m0 = blockIdx.y * 128;
    const int z = blockIdx.z;

    const __half* pA = g_WhQ + (size_t)m0 * C;
    const __half* pB = g_XTh + ((size_t)z * HW + n0) * C;

    auto load_chunk = [&](int stage, int k0) {
        char* sb = smem + stage * DSTG;
#pragma unroll
        for (int it = 0; it < 4; it++) {
            int idx = tid + it * 256;
            int row = idx >> 2, seg = idx & 3;
            const __half* src; int toff; int r;
            if (row < BM) { src = pA; toff = 0;     r = row; }
            else          { src = pB; toff = DTILE; r = row - BM; }
            CP_ASYNC16(smem_u32(sb + toff + r * ROWB + seg * 16),
                       src + (size_t)r * C + k0 + seg * 8);
        }
        CP_COMMIT();
    };

    float acc[4][4][4];
    uint32_t acch[4][4][2];
#pragma unroll
    for (int mi = 0; mi < 4; mi++)
#pragma unroll
        for (int ni = 0; ni < 4; ni++) {
#pragma unroll
            for (int j = 0; j < 4; j++) acc[mi][ni][j] = 0.f;
            acch[mi][ni][0] = 0u; acch[mi][ni][1] = 0u;
        }

    const int NCH = C / KC;   // 16
    load_chunk(0, 0);
    load_chunk(1, KC);
    load_chunk(2, 2 * KC);
#pragma unroll 1
    for (int c = 0; c < NCH; c++) {
        if (c <= NCH - 3)      CP_WAIT2();
        else if (c == NCH - 2) CP_WAIT1();
        else                   CP_WAIT0();
        __syncthreads();
        if (c + 3 < NCH) load_chunk((c + 3) & 3, (c + 3) * KC);
        char* sb = smem + (c & 3) * DSTG;
        uint32_t aH = smem_u32(sb);
        uint32_t bH = aH + DTILE;
#pragma unroll
        for (int ks = 0; ks < 2; ks++) {
            uint32_t ah[4][4], bh[4][2];
            int acol = ks * 16 + (lane >> 4) * 8;
#pragma unroll
            for (int mi = 0; mi < 4; mi++) {
                uint32_t off = (uint32_t)((wm * 64 + mi * 16 + (lane & 15)) * ROWB + acol * 2);
                LDSM_X4(ah[mi], aH + off);
            }
            int l = lane & 15;
            int bcol = ks * 16 + (l >> 3) * 8;
#pragma unroll
            for (int ni = 0; ni < 4; ni++) {
                uint32_t off = (uint32_t)((wn * 32 + ni * 8 + (l & 7)) * ROWB + bcol * 2);
                LDSM_X2(bh[ni], bH + off);
            }
#pragma unroll
            for (int mi = 0; mi < 4; mi++)
#pragma unroll
                for (int ni = 0; ni < 4; ni++)
                    mma_h16(acch[mi][ni], ah[mi], bh[ni]);
        }
        if ((c & 1) == 1) {   // promote every 64 K-values
#pragma unroll
            for (int mi = 0; mi < 4; mi++)
#pragma unroll
                for (int ni = 0; ni < 4; ni++) {
                    float2 lo = __half22float2(*(__half2*)&acch[mi][ni][0]);
                    float2 hi = __half22float2(*(__half2*)&acch[mi][ni][1]);
                    acc[mi][ni][0] += lo.x; acc[mi][ni][1] += lo.y;
                    acc[mi][ni][2] += hi.x; acc[mi][ni][3] += hi.y;
                    acch[mi][ni][0] = 0u;   acch[mi][ni][1] = 0u;
                }
        }
    }

    const int sec = m0 >> 9;
    const float scale = (sec == 0) ? QSCALE : 1.0f;

    __syncthreads();
    if (sec == 2) {
#pragma unroll
        for (int mi = 0; mi < 4; mi++)
#pragma unroll
            for (int ni = 0; ni < 4; ni++) {
                int col = wn * 32 + ni * 8 + (lane & 3) * 2;
#pragma unroll
                for (int hrow = 0; hrow < 2; hrow++) {
                    int r = wm * 64 + mi * 16 + (lane >> 2) + hrow * 8;
                    int mC = (m0 - 1024) + r;
                    float bm = bias[m0 + r];
                    size_t o = ((size_t)(z * HEADS + (mC >> 6)) * DH + (mC & 63)) * HW + n0 + col;
                    *(uint32_t*)&g_Vh[o] = packh(acc[mi][ni][hrow * 2 + 0] + bm,
                                                 acc[mi][ni][hrow * 2 + 1] + bm);
                }
            }
    } else {
        float* ts = (float*)smem;
#pragma unroll
        for (int mi = 0; mi < 4; mi++)
#pragma unroll
            for (int ni = 0; ni < 4; ni++) {
                int col = wn * 32 + ni * 8 + (lane & 3) * 2;
#pragma unroll
                for (int hrow = 0; hrow < 2; hrow++) {
                    int r = wm * 64 + mi * 16 + (lane >> 2) + hrow * 8;
                    float bm = bias[m0 + r];
                    ts[r * 132 + col]     = (acc[mi][ni][hrow * 2 + 0] + bm) * scale;
                    ts[r * 132 + col + 1] = (acc[mi][ni][hrow * 2 + 1] + bm) * scale;
                }
            }
        __syncthreads();
        __half* oh = sec ? g_kTh : g_qTh;
        int h0 = (m0 & 511) >> 6;
#pragma unroll
        for (int it = 0; it < 32; it++) {
            int e = tid + it * 256;
            int i = e & 127;
            int rest = e >> 7;
            int hh = rest & 1, dp = rest >> 1;
            float a  = ts[(hh * 64 + dp * 2)     * 132 + i];
            float bb = ts[(hh * 64 + dp * 2 + 1) * 132 + i];
            size_t o = ((size_t)(z * HEADS + h0 + hh) * HW + n0 + i) * DH + dp * 2;
            *(uint32_t*)&oh[o] = packh(a, bb);
        }
    }
}

// =================== flash attention (f16 accumulators) =======================
#define QROWB   144
#define VROWB   272
#define FQ_TILE 9216
#define FK_TILE 18432
#define FV_TILE 17408
#define FL_STAGEB (FK_TILE + FV_TILE)
#define FL_SMEM (FQ_TILE + 2 * FL_STAGEB) // 80896

__global__ __launch_bounds__(256, 2) void flash_kernel() {
    extern __shared__ char smem[];
    const int tid = threadIdx.x, lane = tid & 31, wid = tid >> 5;
    const int wm = wid & 3;
    const int jw = wid >> 2;
    const int gtid = tid & 127;
    const int barid = 1 + jw;
    const int i0 = blockIdx.x * 64;
    const int bh = blockIdx.y;
    const int b = bh >> 3, h = bh & 7;
    const int wr = wm * 16;
    const uint32_t ONES2[2] = {0x3C003C00u, 0x3C003C00u};

    auto ld_Q = [&]() {
#pragma unroll
        for (int it = 0; it < 2; it++) {
            int idx = tid + it * 256;
            int r = idx >> 3, seg = idx & 7;
            const __half* src = g_qTh + ((size_t)bh * HW + i0 + r) * DH + seg * 8;
            CP_ASYNC16(smem_u32(smem + r * QROWB + seg * 16), src);
        }
    };
    auto ld_KV = [&](int jt, int st) {
        char* sb = smem + FQ_TILE + st * FL_STAGEB;
        int j0 = jt * 128;
#pragma unroll
        for (int it = 0; it < 4; it++) {
            int idx = gtid + it * 128;
            int r = jw * 64 + (idx >> 3), seg = idx & 7;
            const __half* src = g_kTh + ((size_t)bh * HW + j0 + r) * DH + seg * 8;
            CP_ASYNC16(smem_u32(sb + r * QROWB + seg * 16), src);
        }
#pragma unroll
        for (int it = 0; it < 4; it++) {
            int idx = gtid + it * 128;
            int r = idx >> 3, seg = jw * 8 + (idx & 7);
            const __half* src = g_Vh + ((size_t)bh * DH + r) * HW + j0 + seg * 8;
            CP_ASYNC16(smem_u32(sb + FK_TILE + r * VROWB + seg * 16), src);
        }
        CP_COMMIT();
    };

    uint32_t acc_o[8][2];
#pragma unroll
    for (int dt = 0; dt < 8; dt++) { acc_o[dt][0] = 0u; acc_o[dt][1] = 0u; }
    uint32_t lacc[2] = {0u, 0u};
    float mrow0 = -INFINITY, mrow1 = -INFINITY;

    const uint32_t qH = smem_u32(smem);

    ld_Q(); ld_KV(0, 0); CP_COMMIT();
    ld_KV(1, 1);
    CP_WAIT1();
    __syncthreads();

    uint32_t qa[4][4];
#pragma unroll
    for (int ks = 0; ks < 4; ks++) {
        uint32_t aoff = (uint32_t)((wr + (lane & 15)) * QROWB +
                                   (ks * 16 + (lane >> 4) * 8) * 2);
        LDSM_X4(qa[ks], qH + aoff);
    }

    const int krow_l = ((lane >> 4) << 3) + (lane & 7);
    const int kcol_b = ((lane >> 3) & 1) * 8;

#pragma unroll 1
    for (int jt = 0; jt < 8; jt++) {
        uint32_t kb = smem_u32(smem + FQ_TILE + (jt & 1) * FL_STAGEB);
        uint32_t kH = kb;
        uint32_t vH = kb + FK_TILE;

        uint32_t s[8][2];
#pragma unroll
        for (int nt = 0; nt < 8; nt++) { s[nt][0] = 0u; s[nt][1] = 0u; }

#pragma unroll
        for (int ks = 0; ks < 4; ks++) {
            int kcol = ks * 16 + kcol_b;
#pragma unroll
            for (int ntp = 0; ntp < 4; ntp++) {
                uint32_t bh_[4];
                uint32_t boff = (uint32_t)((jw * 64 + ntp * 16 + krow_l) * QROWB + kcol * 2);
                LDSM_X4(bh_, kH + boff);
                mma_h16(s[2 * ntp],     qa[ks], bh_);
                mma_h16(s[2 * ntp + 1], qa[ks], bh_ + 2);
            }
        }

        // ---- online softmax (log2 domain, half2) ----
        uint32_t m0p = s[0][0], m1p = s[0][1];
#pragma unroll
        for (int nt = 1; nt < 8; nt++) {
            m0p = hmax2u(m0p, s[nt][0]);
            m1p = hmax2u(m1p, s[nt][1]);
        }
        m0p = hmax2u(m0p, __shfl_xor_sync(0xffffffffu, m0p, 1));
        m0p = hmax2u(m0p, __shfl_xor_sync(0xffffffffu, m0p, 2));
        m1p = hmax2u(m1p, __shfl_xor_sync(0xffffffffu, m1p, 1));
        m1p = hmax2u(m1p, __shfl_xor_sync(0xffffffffu, m1p, 2));
        __half2 m0h = *(__half2*)&m0p, m1h = *(__half2*)&m1p;
        float mx0 = __half2float(__hmax(__low2half(m0h), __high2half(m0h)));
        float mx1 = __half2float(__hmax(__low2half(m1h), __high2half(m1h)));
        float mn0 = fmaxf(mrow0, mx0), mn1 = fmaxf(mrow1, mx1);
        float al0 = ex2f(mrow0 - mn0), al1 = ex2f(mrow1 - mn1);
        mrow0 = mn0; mrow1 = mn1;
        uint32_t al02 = packh(al0, al0), al12 = packh(al1, al1);
#pragma unroll
        for (int dt = 0; dt < 8; dt++) {
            acc_o[dt][0] = hmul2u(acc_o[dt][0], al02);
            acc_o[dt][1] = hmul2u(acc_o[dt][1], al12);
        }
        lacc[0] = hmul2u(lacc[0], al02);
        lacc[1] = hmul2u(lacc[1], al12);

        uint32_t mn02 = packh(mn0, mn0), mn12 = packh(mn1, mn1);
#pragma unroll
        for (int nt = 0; nt < 8; nt++) {
            s[nt][0] = ex2h2(hsub2u(s[nt][0], mn02));
            s[nt][1] = ex2h2(hsub2u(s[nt][1], mn12));
        }

#pragma unroll
        for (int kk = 0; kk < 4; kk++) {
            uint32_t aph[4];
            aph[0] = s[2 * kk][0];     aph[1] = s[2 * kk][1];
            aph[2] = s[2 * kk + 1][0]; aph[3] = s[2 * kk + 1][1];
            mma_h16(lacc, aph, ONES2);
            int vcol = jw * 64 + kk * 16 + kcol_b;
#pragma unroll
            for (int dt = 0; dt < 4; dt++) {
                uint32_t bvh[4];
                uint32_t off = (uint32_t)((dt * 16 + krow_l) * VROWB + vcol * 2);
                LDSM_X4(bvh, vH + off);
                mma_h16(acc_o[2 * dt],     aph, bvh);
                mma_h16(acc_o[2 * dt + 1], aph, bvh + 2);
            }
        }

        BAR_GROUP(barid);
        if (jt + 2 < 8)      { ld_KV(jt + 2, jt & 1); CP_WAIT1(); }
        else if (jt + 1 < 8) { CP_WAIT0(); }
        BAR_GROUP(barid);
    }

    float lrow0 = __half2float(__low2half(*(__half2*)&lacc[0]));
    float lrow1 = __half2float(__low2half(*(__half2*)&lacc[1]));

    float ao[8][4];
#pragma unroll
    for (int dt = 0; dt < 8; dt++) {
        float2 lo = __half22float2(*(__half2*)&acc_o[dt][0]);
        float2 hi = __half22float2(*(__half2*)&acc_o[dt][1]);
        ao[dt][0] = lo.x; ao[dt][1] = lo.y;
        ao[dt][2] = hi.x; ao[dt][3] = hi.y;
    }

    __syncthreads();
    float* mo = (float*)smem;
    float* ml = (float*)(smem + 64 * 68 * 4);
    float* ll = ml + 64;
    int r0 = wr + (lane >> 2);
    int cb = (lane & 3) * 2;

    if (jw == 1) {
#pragma unroll
        for (int dt = 0; dt < 8; dt++) {
            mo[r0 * 68 + dt * 8 + cb]           = ao[dt][0];
            mo[r0 * 68 + dt * 8 + cb + 1]       = ao[dt][1];
            mo[(r0 + 8) * 68 + dt * 8 + cb]     = ao[dt][2];
            mo[(r0 + 8) * 68 + dt * 8 + cb + 1] = ao[dt][3];
        }
        if ((lane & 3) == 0) {
            ml[r0] = mrow0; ml[r0 + 8] = mrow1;
            ll[r0] = lrow0; ll[r0 + 8] = lrow1;
        }
    }
    __syncthreads();
    if (jw == 0) {
        float mB0 = ml[r0],     lB0 = ll[r0];
        float mB1 = ml[r0 + 8], lB1 = ll[r0 + 8];
        float m0 = fmaxf(mrow0, mB0), m1 = fmaxf(mrow1, mB1);
        float a0 = ex2f(mrow0 - m0), b0 = ex2f(mB0 - m0);
        float a1 = ex2f(mrow1 - m1), b1 = ex2f(mB1 - m1);
        float inv0 = 1.f / (lrow0 * a0 + lB0 * b0);
        float inv1 = 1.f / (lrow1 * a1 + lB1 * b1);
        int cbase = h * DH + cb;
#pragma unroll
        for (int dt = 0; dt < 8; dt++) {
            float ox = (ao[dt][0] * a0 + mo[r0 * 68 + dt * 8 + cb]     * b0) * inv0;
            float oy = (ao[dt][1] * a0 + mo[r0 * 68 + dt * 8 + cb + 1] * b0) * inv0;
            size_t o0 = ((size_t)b * HW + i0 + r0) * C + cbase + dt * 8;
            *(uint32_t*)&g_AOTh[o0] = packh(ox, oy);
            ox = (ao[dt][2] * a1 + mo[(r0 + 8) * 68 + dt * 8 + cb]     * b1) * inv1;
            oy = (ao[dt][3] * a1 + mo[(r0 + 8) * 68 + dt * 8 + cb + 1] * b1) * inv1;
            size_t o1 = ((size_t)b * HW + i0 + r0 + 8) * C + cbase + dt * 8;
            *(uint32_t*)&g_AOTh[o1] = packh(ox, oy);
        }
    }
}

// =================== proj GEMM (f16-acc + promote, +bias +residual) ===========
__global__ __launch_bounds__(256, 2) void proj_gemm(const float* __restrict__ bias,
                                                    const float* __restrict__ resid,
                                                    float* __restrict__ out) {
    constexpr int BM = 128;
    extern __shared__ char smem[];

    const int tid = threadIdx.x;
    const int lane = tid & 31, wid = tid >> 5;
    const int wm = wid & 1, wn = wid >> 1;
    const int n0 = blockIdx.x * 128, m0 = blockIdx.y * 128;
    const int z = blockIdx.z;

    const __half* pA = g_WhP + (size_t)m0 * C;
    const __half* pB = g_AOTh + ((size_t)z * HW + n0) * C;

    auto load_chunk = [&](int stage, int k0) {
        char* sb = smem + stage * DSTG;
#pragma unroll
        for (int it = 0; it < 4; it++) {
            int idx = tid + it * 256;
            int row = idx >> 2, seg = idx & 3;
            const __half* src; int toff; int r;
            if (row < BM) { src = pA; toff = 0;     r = row; }
            else          { src = pB; toff = DTILE; r = row - BM; }
            CP_ASYNC16(smem_u32(sb + toff + r * ROWB + seg * 16),
                       src + (size_t)r * C + k0 + seg * 8);
        }
        CP_COMMIT();
    };

    float acc[4][4][4];
    uint32_t acch[4][4][2];
#pragma unroll
    for (int mi = 0; mi < 4; mi++)
#pragma unroll
        for (int ni = 0; ni < 4; ni++) {
#pragma unroll
            for (int j = 0; j < 4; j++) acc[mi][ni][j] = 0.f;
            acch[mi][ni][0] = 0u; acch[mi][ni][1] = 0u;
        }

    const int NCH = C / KC;
    load_chunk(0, 0);
    load_chunk(1, KC);
    load_chunk(2, 2 * KC);
#pragma unroll 1
    for (int c = 0; c < NCH; c++) {
        if (c <= NCH - 3)      CP_WAIT2();
        else if (c == NCH - 2) CP_WAIT1();
        else                   CP_WAIT0();
        __syncthreads();
        if (c + 3 < NCH) load_chunk((c + 3) & 3, (c + 3) * KC);
        char* sb = smem + (c & 3) * DSTG;
        uint32_t aH = smem_u32(sb);
        uint32_t bH = aH + DTILE;
#pragma unroll
        for (int ks = 0; ks < 2; ks++) {
            uint32_t ah[4][4], bh[4][2];
            int acol = ks * 16 + (lane >> 4) * 8;
#pragma unroll
            for (int mi = 0; mi < 4; mi++) {
                uint32_t off = (uint32_t)((wm * 64 + mi * 16 + (lane & 15)) * ROWB + acol * 2);
                LDSM_X4(ah[mi], aH + off);
            }
            int l = lane & 15;
            int bcol = ks * 16 + (l >> 3) * 8;
#pragma unroll
            for (int ni = 0; ni < 4; ni++) {
                uint32_t off = (uint32_t)((wn * 32 + ni * 8 + (l & 7)) * ROWB + bcol * 2);
                LDSM_X2(bh[ni], bH + off);
            }
#pragma unroll
            for (int mi = 0; mi < 4; mi++)
#pragma unroll
                for (int ni = 0; ni < 4; ni++)
                    mma_h16(acch[mi][ni], ah[mi], bh[ni]);
        }
        if ((c & 1) == 1) {
#pragma unroll
            for (int mi = 0; mi < 4; mi++)
#pragma unroll
                for (int ni = 0; ni < 4; ni++) {
                    float2 lo = __half22float2(*(__half2*)&acch[mi][ni][0]);
                    float2 hi = __half22float2(*(__half2*)&acch[mi][ni][1]);
                    acc[mi][ni][0] += lo.x; acc[mi][ni][1] += lo.y;
                    acc[mi][ni][2] += hi.x; acc[mi][ni][3] += hi.y;
                    acch[mi][ni][0] = 0u;   acch[mi][ni][1] = 0u;
                }
        }
    }

    float* po = out + (size_t)z * C * HW;
#pragma unroll
    for (int mi = 0; mi < 4; mi++)
#pragma unroll
        for (int ni = 0; ni < 4; ni++) {
            int col = n0 + wn * 32 + ni * 8 + (lane & 3) * 2;
#pragma unroll
            for (int hrow = 0; hrow < 2; hrow++) {
                int r = m0 + wm * 64 + mi * 16 + (lane >> 2) + hrow * 8;
                float bm = bias[r];
                size_t off = (size_t)r * HW + col;
                float2 rx = *(const float2*)&resid[(size_t)z * C * HW + off];
                float2 v;
                v.x = acc[mi][ni][hrow * 2 + 0] + bm + rx.x;
                v.y = acc[mi][ni][hrow * 2 + 1] + bm + rx.y;
                *(float2*)&po[off] = v;
            }
        }
}

// =================== launch ===================================================
extern "C" void kernel_launch(void* const* d_in, const int* in_sizes, int n_in,
                              void* d_out, int out_size) {
    const float* x      = (const float*)d_in[0];
    const float* gn_w   = (const float*)d_in[1];
    const float* gn_b   = (const float*)d_in[2];
    const float* qkv_w  = (const float*)d_in[3];
    const float* qkv_b  = (const float*)d_in[4];
    const float* proj_w = (const float*)d_in[5];
    const float* proj_b = (const float*)d_in[6];
    float* out = (float*)d_out;

    static bool init = false;
    if (!init) {
        cudaFuncSetAttribute(qkv_gemm, cudaFuncAttributeMaxDynamicSharedMemorySize, SMQKV);
        cudaFuncSetAttribute(proj_gemm, cudaFuncAttributeMaxDynamicSharedMemorySize, SMPROJ);
        cudaFuncSetAttribute(flash_kernel, cudaFuncAttributeMaxDynamicSharedMemorySize, FL_SMEM);
        init = true;
    }

    prep_kernel<<<1280, 256>>>(x, qkv_w, proj_w);
    convT_kernel<<<dim3(HW / 32, C / 32, B), dim3(32, 8)>>>(x, gn_w, gn_b);

    qkv_gemm<<<dim3(HW / 128, 3 * C / 128, B), 256, SMQKV>>>(qkv_b);

    flash_kernel<<<dim3(HW / 64, B * HEADS), 256, FL_SMEM>>>();

    proj_gemm<<<dim3(HW / 128, C / 128, B), 256, SMPROJ>>>(proj_b, x, out);
}

// round 14
// speedup vs baseline: 1.1462x; 1.1462x over previous
#include <cuda_runtime.h>
#include <cuda_fp16.h>
#include <cstdint>
#include <math.h>

#define B    8
#define C    512
#define HW   1024
#define G    32
#define CPG  16
#define HEADS 8
#define DH   64
#define EPS  1e-5f
#define QSCALE 0.1803368867f   // 0.125 * log2(e)

// ---------------- scratch (device globals) ----------------------------------
__device__ float2 g_stats[B * G];

__device__ __half g_WhQ[3 * C * C];
__device__ __half g_WhP[C * C];
__device__ __half g_XTh [B * HW * C];          // [b][n][c]
__device__ __half g_AOTh[B * HW * C];          // [b][i][c]
__device__ __half g_qTh [B * HEADS * HW * DH]; // [bh][i][d] (log2-scaled)
__device__ __half g_kTh [B * HEADS * HW * DH]; // [bh][j][d]
__device__ __half g_Vh  [B * HEADS * DH * HW]; // [bh][d][j]

// =================== helpers ==================================================
__device__ __forceinline__ uint32_t smem_u32(const void* p) {
    uint32_t r;
    asm("{ .reg .u64 t; cvta.to.shared.u64 t, %1; cvt.u32.u64 %0, t; }"
        : "=r"(r) : "l"(p));
    return r;
}
#define CP_ASYNC16(dst, src) \
    asm volatile("cp.async.cg.shared.global [%0], [%1], 16;" :: "r"(dst), "l"(src) : "memory")
#define CP_COMMIT() asm volatile("cp.async.commit_group;" ::: "memory")
#define CP_WAIT2()  asm volatile("cp.async.wait_group 2;" ::: "memory")
#define CP_WAIT1()  asm volatile("cp.async.wait_group 1;" ::: "memory")
#define CP_WAIT0()  asm volatile("cp.async.wait_group 0;" ::: "memory")
#define BAR_GROUP(id) asm volatile("bar.sync %0, %1;" :: "r"(id), "r"(128) : "memory")

#define LDSM_X4(r, addr) \
    asm volatile("ldmatrix.sync.aligned.m8n8.x4.shared.b16 {%0,%1,%2,%3}, [%4];" \
        : "=r"((r)[0]), "=r"((r)[1]), "=r"((r)[2]), "=r"((r)[3]) : "r"(addr))
#define LDSM_X2(r, addr) \
    asm volatile("ldmatrix.sync.aligned.m8n8.x2.shared.b16 {%0,%1}, [%2];" \
        : "=r"((r)[0]), "=r"((r)[1]) : "r"(addr))

__device__ __forceinline__ void mma_f16(float* c, const uint32_t* a, const uint32_t* b) {
    asm volatile(
        "mma.sync.aligned.m16n8k16.row.col.f32.f16.f16.f32 "
        "{%0,%1,%2,%3}, {%4,%5,%6,%7}, {%8,%9}, {%0,%1,%2,%3};"
        : "+f"(c[0]), "+f"(c[1]), "+f"(c[2]), "+f"(c[3])
        : "r"(a[0]), "r"(a[1]), "r"(a[2]), "r"(a[3]), "r"(b[0]), "r"(b[1]));
}
// f16-accumulate MMA: D,C packed half2 (2 regs)
__device__ __forceinline__ void mma_h16(uint32_t* c, const uint32_t* a, const uint32_t* b) {
    asm volatile(
        "mma.sync.aligned.m16n8k16.row.col.f16.f16.f16.f16 "
        "{%0,%1}, {%2,%3,%4,%5}, {%6,%7}, {%0,%1};"
        : "+r"(c[0]), "+r"(c[1])
        : "r"(a[0]), "r"(a[1]), "r"(a[2]), "r"(a[3]), "r"(b[0]), "r"(b[1]));
}
__device__ __forceinline__ uint32_t packh(float x, float y) {
    __half2 h = __floats2half2_rn(x, y);
    return *(uint32_t*)&h;
}
__device__ __forceinline__ float ex2f(float x) {
    float y;
    asm("ex2.approx.f32 %0, %1;" : "=f"(y) : "f"(x));
    return y;
}
__device__ __forceinline__ uint32_t ex2h2(uint32_t x) {
    uint32_t y;
    asm("ex2.approx.f16x2 %0, %1;" : "=r"(y) : "r"(x));
    return y;
}
__device__ __forceinline__ uint32_t hmax2u(uint32_t a, uint32_t b) {
    __half2 r = __hmax2(*(__half2*)&a, *(__half2*)&b);
    return *(uint32_t*)&r;
}
__device__ __forceinline__ uint32_t hmul2u(uint32_t a, uint32_t b) {
    __half2 r = __hmul2(*(__half2*)&a, *(__half2*)&b);
    return *(uint32_t*)&r;
}
__device__ __forceinline__ uint32_t hsub2u(uint32_t a, uint32_t b) {
    __half2 r = __hsub2(*(__half2*)&a, *(__half2*)&b);
    return *(uint32_t*)&r;
}

// =========== fused prologue: gn stats + both weight converts ==================
__global__ __launch_bounds__(256) void prep_kernel(const float* __restrict__ x,
                                                   const float* __restrict__ qkv_w,
                                                   const float* __restrict__ proj_w) {
    int blk = blockIdx.x;
    if (blk < 256) {
        const float4* xp = (const float4*)(x + (size_t)blk * CPG * HW);
        const int N4 = CPG * HW / 4;
        float s = 0.f, s2 = 0.f;
        for (int i = threadIdx.x; i < N4; i += 256) {
            float4 v = xp[i];
            s  += v.x + v.y + v.z + v.w;
            s2 += v.x * v.x + v.y * v.y + v.z * v.z + v.w * v.w;
        }
        __shared__ float sh1[8], sh2[8];
        int lane = threadIdx.x & 31, wid = threadIdx.x >> 5;
        for (int o = 16; o; o >>= 1) {
            s  += __shfl_down_sync(0xffffffffu, s,  o);
            s2 += __shfl_down_sync(0xffffffffu, s2, o);
        }
        if (lane == 0) { sh1[wid] = s; sh2[wid] = s2; }
        __syncthreads();
        if (threadIdx.x == 0) {
            for (int i = 1; i < 8; i++) { sh1[0] += sh1[i]; sh2[0] += sh2[i]; }
            const float N = CPG * HW;
            float mean = sh1[0] * (1.f / N);
            float var  = sh2[0] * (1.f / N) - mean * mean;
            g_stats[blk] = make_float2(mean, rsqrtf(var + EPS));
        }
    } else if (blk < 1024) {
        int i = (blk - 256) * 1024 + threadIdx.x * 4;
        float4 v = *(const float4*)&qkv_w[i];
        *(uint32_t*)&g_WhQ[i]     = packh(v.x, v.y);
        *(uint32_t*)&g_WhQ[i + 2] = packh(v.z, v.w);
    } else {
        int i = (blk - 1024) * 1024 + threadIdx.x * 4;
        float4 v = *(const float4*)&proj_w[i];
        *(uint32_t*)&g_WhP[i]     = packh(v.x, v.y);
        *(uint32_t*)&g_WhP[i + 2] = packh(v.z, v.w);
    }
}

// ===== fused GN-apply + transpose + convert ===================================
__global__ __launch_bounds__(256) void convT_kernel(const float* __restrict__ x,
                                                    const float* __restrict__ gw,
                                                    const float* __restrict__ gb) {
    __shared__ float t[32][33];
    int n0 = blockIdx.x * 32, c0 = blockIdx.y * 32, b = blockIdx.z;
    const float* ip = x + (size_t)b * C * HW;
    int tx = threadIdx.x, ty = threadIdx.y;
#pragma unroll
    for (int k = 0; k < 4; k++) {
        int ch = c0 + ty + k * 8;
        float2 st = g_stats[b * G + (ch >> 4)];
        float v = ip[(size_t)ch * HW + n0 + tx];
        t[ty + k * 8][tx] = (v - st.x) * st.y * gw[ch] + gb[ch];
    }
    __syncthreads();
#pragma unroll
    for (int k = 0; k < 4; k++) {
        int ni = ty + k * 8;
        size_t o = (size_t)b * HW * C + (size_t)(n0 + ni) * C + c0 + tx;
        g_XTh[o] = __float2half(t[tx][ni]);
    }
}

// =================== dense GEMM config (4-stage, 2 CTA/SM) ====================
#define KC    32
#define ROWB  80
#define DTILE (128 * ROWB)
#define DSTG  (2 * DTILE)
#define SMQKV 81920
#define SMPROJ 81920
#define TSP   133        // fp32 staging pitch (2-way instead of 8-way conflicts)

// =================== QKV GEMM =================================================
__global__ __launch_bounds__(256, 2) void qkv_gemm(const float* __restrict__ bias) {
    constexpr int BM = 128;
    extern __shared__ char smem[];

    const int tid = threadIdx.x;
    const int lane = tid & 31, wid = tid >> 5;
    const int wm = wid & 1, wn = wid >> 1;
    const int n0 = blockIdx.x * 128, m0 = blockIdx.y * 128;
    const int z = blockIdx.z;

    const __half* pA = g_WhQ + (size_t)m0 * C;
    const __half* pB = g_XTh + ((size_t)z * HW + n0) * C;

    auto load_chunk = [&](int stage, int k0) {
        char* sb = smem + stage * DSTG;
#pragma unroll
        for (int it = 0; it < 4; it++) {
            int idx = tid + it * 256;
            int row = idx >> 2, seg = idx & 3;
            const __half* src; int toff; int r;
            if (row < BM) { src = pA; toff = 0;     r = row; }
            else          { src = pB; toff = DTILE; r = row - BM; }
            CP_ASYNC16(smem_u32(sb + toff + r * ROWB + seg * 16),
                       src + (size_t)r * C + k0 + seg * 8);
        }
        CP_COMMIT();
    };

    float acc[4][4][4];
#pragma unroll
    for (int mi = 0; mi < 4; mi++)
#pragma unroll
        for (int ni = 0; ni < 4; ni++)
#pragma unroll
            for (int j = 0; j < 4; j++) acc[mi][ni][j] = 0.f;

    const int NCH = C / KC;
    load_chunk(0, 0);
    load_chunk(1, KC);
    load_chunk(2, 2 * KC);
#pragma unroll 1
    for (int c = 0; c < NCH; c++) {
        if (c <= NCH - 3)      CP_WAIT2();
        else if (c == NCH - 2) CP_WAIT1();
        else                   CP_WAIT0();
        __syncthreads();
        if (c + 3 < NCH) load_chunk((c + 3) & 3, (c + 3) * KC);
        char* sb = smem + (c & 3) * DSTG;
        uint32_t aH = smem_u32(sb);
        uint32_t bH = aH + DTILE;
#pragma unroll
        for (int ks = 0; ks < 2; ks++) {
            uint32_t ah[4][4], bh[4][2];
            int acol = ks * 16 + (lane >> 4) * 8;
#pragma unroll
            for (int mi = 0; mi < 4; mi++) {
                uint32_t off = (uint32_t)((wm * 64 + mi * 16 + (lane & 15)) * ROWB + acol * 2);
                LDSM_X4(ah[mi], aH + off);
            }
            int l = lane & 15;
            int bcol = ks * 16 + (l >> 3) * 8;
#pragma unroll
            for (int ni = 0; ni < 4; ni++) {
                uint32_t off = (uint32_t)((wn * 32 + ni * 8 + (l & 7)) * ROWB + bcol * 2);
                LDSM_X2(bh[ni], bH + off);
            }
#pragma unroll
            for (int mi = 0; mi < 4; mi++)
#pragma unroll
                for (int ni = 0; ni < 4; ni++)
                    mma_f16(acc[mi][ni], ah[mi], bh[ni]);
        }
    }

    const int sec = m0 >> 9;
    const float scale = (sec == 0) ? QSCALE : 1.0f;

    __syncthreads();
    if (sec == 2) {
#pragma unroll
        for (int mi = 0; mi < 4; mi++)
#pragma unroll
            for (int ni = 0; ni < 4; ni++) {
                int col = wn * 32 + ni * 8 + (lane & 3) * 2;
#pragma unroll
                for (int hrow = 0; hrow < 2; hrow++) {
                    int r = wm * 64 + mi * 16 + (lane >> 2) + hrow * 8;
                    int mC = (m0 - 1024) + r;
                    float bm = bias[m0 + r];
                    size_t o = ((size_t)(z * HEADS + (mC >> 6)) * DH + (mC & 63)) * HW + n0 + col;
                    *(uint32_t*)&g_Vh[o] = packh(acc[mi][ni][hrow * 2 + 0] + bm,
                                                 acc[mi][ni][hrow * 2 + 1] + bm);
                }
            }
    } else {
        float* ts = (float*)smem;
#pragma unroll
        for (int mi = 0; mi < 4; mi++)
#pragma unroll
            for (int ni = 0; ni < 4; ni++) {
                int col = wn * 32 + ni * 8 + (lane & 3) * 2;
#pragma unroll
                for (int hrow = 0; hrow < 2; hrow++) {
                    int r = wm * 64 + mi * 16 + (lane >> 2) + hrow * 8;
                    float bm = bias[m0 + r];
                    ts[r * TSP + col]     = (acc[mi][ni][hrow * 2 + 0] + bm) * scale;
                    ts[r * TSP + col + 1] = (acc[mi][ni][hrow * 2 + 1] + bm) * scale;
                }
            }
        __syncthreads();
        __half* oh = sec ? g_kTh : g_qTh;
        int h0 = (m0 & 511) >> 6;
        // lane -> dp axis: each warp writes one (i,hh) as a contiguous 128B txn
#pragma unroll
        for (int it = 0; it < 32; it++) {
            int e = tid + it * 256;
            int dp = e & 31;
            int i  = (e >> 5) & 127;
            int hh = e >> 12;
            float a  = ts[(hh * 64 + dp * 2)     * TSP + i];
            float bb = ts[(hh * 64 + dp * 2 + 1) * TSP + i];
            size_t o = ((size_t)(z * HEADS + h0 + hh) * HW + n0 + i) * DH + dp * 2;
            *(uint32_t*)&oh[o] = packh(a, bb);
        }
    }
}

// =================== flash attention (f16 accumulators) =======================
#define QROWB   144
#define VROWB   272
#define FQ_TILE 9216
#define FK_TILE 18432
#define FV_TILE 17408
#define FL_STAGEB (FK_TILE + FV_TILE)
#define FL_SMEM (FQ_TILE + 2 * FL_STAGEB) // 80896

__global__ __launch_bounds__(256, 2) void flash_kernel() {
    extern __shared__ char smem[];
    const int tid = threadIdx.x, lane = tid & 31, wid = tid >> 5;
    const int wm = wid & 3;
    const int jw = wid >> 2;
    const int gtid = tid & 127;
    const int barid = 1 + jw;
    const int i0 = blockIdx.x * 64;
    const int bh = blockIdx.y;
    const int b = bh >> 3, h = bh & 7;
    const int wr = wm * 16;
    const uint32_t ONES2[2] = {0x3C003C00u, 0x3C003C00u};

    auto ld_Q = [&]() {
#pragma unroll
        for (int it = 0; it < 2; it++) {
            int idx = tid + it * 256;
            int r = idx >> 3, seg = idx & 7;
            const __half* src = g_qTh + ((size_t)bh * HW + i0 + r) * DH + seg * 8;
            CP_ASYNC16(smem_u32(smem + r * QROWB + seg * 16), src);
        }
    };
    auto ld_KV = [&](int jt, int st) {
        char* sb = smem + FQ_TILE + st * FL_STAGEB;
        int j0 = jt * 128;
#pragma unroll
        for (int it = 0; it < 4; it++) {
            int idx = gtid + it * 128;
            int r = jw * 64 + (idx >> 3), seg = idx & 7;
            const __half* src = g_kTh + ((size_t)bh * HW + j0 + r) * DH + seg * 8;
            CP_ASYNC16(smem_u32(sb + r * QROWB + seg * 16), src);
        }
#pragma unroll
        for (int it = 0; it < 4; it++) {
            int idx = gtid + it * 128;
            int r = idx >> 3, seg = jw * 8 + (idx & 7);
            const __half* src = g_Vh + ((size_t)bh * DH + r) * HW + j0 + seg * 8;
            CP_ASYNC16(smem_u32(sb + FK_TILE + r * VROWB + seg * 16), src);
        }
        CP_COMMIT();
    };

    uint32_t acc_o[8][2];
#pragma unroll
    for (int dt = 0; dt < 8; dt++) { acc_o[dt][0] = 0u; acc_o[dt][1] = 0u; }
    uint32_t lacc[2] = {0u, 0u};
    float mrow0 = -INFINITY, mrow1 = -INFINITY;

    const uint32_t qH = smem_u32(smem);

    ld_Q(); ld_KV(0, 0); CP_COMMIT();
    ld_KV(1, 1);
    CP_WAIT1();
    __syncthreads();

    uint32_t qa[4][4];
#pragma unroll
    for (int ks = 0; ks < 4; ks++) {
        uint32_t aoff = (uint32_t)((wr + (lane & 15)) * QROWB +
                                   (ks * 16 + (lane >> 4) * 8) * 2);
        LDSM_X4(qa[ks], qH + aoff);
    }

    const int krow_l = ((lane >> 4) << 3) + (lane & 7);
    const int kcol_b = ((lane >> 3) & 1) * 8;

#pragma unroll 1
    for (int jt = 0; jt < 8; jt++) {
        uint32_t kb = smem_u32(smem + FQ_TILE + (jt & 1) * FL_STAGEB);
        uint32_t kH = kb;
        uint32_t vH = kb + FK_TILE;

        uint32_t s[8][2];
#pragma unroll
        for (int nt = 0; nt < 8; nt++) { s[nt][0] = 0u; s[nt][1] = 0u; }

#pragma unroll
        for (int ks = 0; ks < 4; ks++) {
            int kcol = ks * 16 + kcol_b;
#pragma unroll
            for (int ntp = 0; ntp < 4; ntp++) {
                uint32_t bh_[4];
                uint32_t boff = (uint32_t)((jw * 64 + ntp * 16 + krow_l) * QROWB + kcol * 2);
                LDSM_X4(bh_, kH + boff);
                mma_h16(s[2 * ntp],     qa[ks], bh_);
                mma_h16(s[2 * ntp + 1], qa[ks], bh_ + 2);
            }
        }

        // ---- online softmax (log2 domain, half2) ----
        uint32_t m0p = s[0][0], m1p = s[0][1];
#pragma unroll
        for (int nt = 1; nt < 8; nt++) {
            m0p = hmax2u(m0p, s[nt][0]);
            m1p = hmax2u(m1p, s[nt][1]);
        }
        m0p = hmax2u(m0p, __shfl_xor_sync(0xffffffffu, m0p, 1));
        m0p = hmax2u(m0p, __shfl_xor_sync(0xffffffffu, m0p, 2));
        m1p = hmax2u(m1p, __shfl_xor_sync(0xffffffffu, m1p, 1));
        m1p = hmax2u(m1p, __shfl_xor_sync(0xffffffffu, m1p, 2));
        __half2 m0h = *(__half2*)&m0p, m1h = *(__half2*)&m1p;
        float mx0 = __half2float(__hmax(__low2half(m0h), __high2half(m0h)));
        float mx1 = __half2float(__hmax(__low2half(m1h), __high2half(m1h)));
        float mn0 = fmaxf(mrow0, mx0), mn1 = fmaxf(mrow1, mx1);
        float al0 = ex2f(mrow0 - mn0), al1 = ex2f(mrow1 - mn1);
        mrow0 = mn0; mrow1 = mn1;
        uint32_t al02 = packh(al0, al0), al12 = packh(al1, al1);
#pragma unroll
        for (int dt = 0; dt < 8; dt++) {
            acc_o[dt][0] = hmul2u(acc_o[dt][0], al02);
            acc_o[dt][1] = hmul2u(acc_o[dt][1], al12);
        }
        lacc[0] = hmul2u(lacc[0], al02);
        lacc[1] = hmul2u(lacc[1], al12);

        uint32_t mn02 = packh(mn0, mn0), mn12 = packh(mn1, mn1);
#pragma unroll
        for (int nt = 0; nt < 8; nt++) {
            s[nt][0] = ex2h2(hsub2u(s[nt][0], mn02));
            s[nt][1] = ex2h2(hsub2u(s[nt][1], mn12));
        }

#pragma unroll
        for (int kk = 0; kk < 4; kk++) {
            uint32_t aph[4];
            aph[0] = s[2 * kk][0];     aph[1] = s[2 * kk][1];
            aph[2] = s[2 * kk + 1][0]; aph[3] = s[2 * kk + 1][1];
            mma_h16(lacc, aph, ONES2);
            int vcol = jw * 64 + kk * 16 + kcol_b;
#pragma unroll
            for (int dt = 0; dt < 4; dt++) {
                uint32_t bvh[4];
                uint32_t off = (uint32_t)((dt * 16 + krow_l) * VROWB + vcol * 2);
                LDSM_X4(bvh, vH + off);
                mma_h16(acc_o[2 * dt],     aph, bvh);
                mma_h16(acc_o[2 * dt + 1], aph, bvh + 2);
            }
        }

        BAR_GROUP(barid);
        if (jt + 2 < 8)      { ld_KV(jt + 2, jt & 1); CP_WAIT1(); }
        else if (jt + 1 < 8) { CP_WAIT0(); }
        BAR_GROUP(barid);
    }

    float lrow0 = __half2float(__low2half(*(__half2*)&lacc[0]));
    float lrow1 = __half2float(__low2half(*(__half2*)&lacc[1]));

    float ao[8][4];
#pragma unroll
    for (int dt = 0; dt < 8; dt++) {
        float2 lo = __half22float2(*(__half2*)&acc_o[dt][0]);
        float2 hi = __half22float2(*(__half2*)&acc_o[dt][1]);
        ao[dt][0] = lo.x; ao[dt][1] = lo.y;
        ao[dt][2] = hi.x; ao[dt][3] = hi.y;
    }

    __syncthreads();
    float* mo = (float*)smem;
    float* ml = (float*)(smem + 64 * 68 * 4);
    float* ll = ml + 64;
    int r0 = wr + (lane >> 2);
    int cb = (lane & 3) * 2;

    if (jw == 1) {
#pragma unroll
        for (int dt = 0; dt < 8; dt++) {
            mo[r0 * 68 + dt * 8 + cb]           = ao[dt][0];
            mo[r0 * 68 + dt * 8 + cb + 1]       = ao[dt][1];
            mo[(r0 + 8) * 68 + dt * 8 + cb]     = ao[dt][2];
            mo[(r0 + 8) * 68 + dt * 8 + cb + 1] = ao[dt][3];
        }
        if ((lane & 3) == 0) {
            ml[r0] = mrow0; ml[r0 + 8] = mrow1;
            ll[r0] = lrow0; ll[r0 + 8] = lrow1;
        }
    }
    __syncthreads();
    if (jw == 0) {
        float mB0 = ml[r0],     lB0 = ll[r0];
        float mB1 = ml[r0 + 8], lB1 = ll[r0 + 8];
        float m0 = fmaxf(mrow0, mB0), m1 = fmaxf(mrow1, mB1);
        float a0 = ex2f(mrow0 - m0), b0 = ex2f(mB0 - m0);
        float a1 = ex2f(mrow1 - m1), b1 = ex2f(mB1 - m1);
        float inv0 = 1.f / (lrow0 * a0 + lB0 * b0);
        float inv1 = 1.f / (lrow1 * a1 + lB1 * b1);
        int cbase = h * DH + cb;
#pragma unroll
        for (int dt = 0; dt < 8; dt++) {
            float ox = (ao[dt][0] * a0 + mo[r0 * 68 + dt * 8 + cb]     * b0) * inv0;
            float oy = (ao[dt][1] * a0 + mo[r0 * 68 + dt * 8 + cb + 1] * b0) * inv0;
            size_t o0 = ((size_t)b * HW + i0 + r0) * C + cbase + dt * 8;
            *(uint32_t*)&g_AOTh[o0] = packh(ox, oy);
            ox = (ao[dt][2] * a1 + mo[(r0 + 8) * 68 + dt * 8 + cb]     * b1) * inv1;
            oy = (ao[dt][3] * a1 + mo[(r0 + 8) * 68 + dt * 8 + cb + 1] * b1) * inv1;
            size_t o1 = ((size_t)b * HW + i0 + r0 + 8) * C + cbase + dt * 8;
            *(uint32_t*)&g_AOTh[o1] = packh(ox, oy);
        }
    }
}

// =================== proj GEMM ================================================
__global__ __launch_bounds__(256, 2) void proj_gemm(const float* __restrict__ bias,
                                                    const float* __restrict__ resid,
                                                    float* __restrict__ out) {
    constexpr int BM = 128;
    extern __shared__ char smem[];

    const int tid = threadIdx.x;
    const int lane = tid & 31, wid = tid >> 5;
    const int wm = wid & 1, wn = wid >> 1;
    const int n0 = blockIdx.x * 128, m0 = blockIdx.y * 128;
    const int z = blockIdx.z;

    const __half* pA = g_WhP + (size_t)m0 * C;
    const __half* pB = g_AOTh + ((size_t)z * HW + n0) * C;

    auto load_chunk = [&](int stage, int k0) {
        char* sb = smem + stage * DSTG;
#pragma unroll
        for (int it = 0; it < 4; it++) {
            int idx = tid + it * 256;
            int row = idx >> 2, seg = idx & 3;
            const __half* src; int toff; int r;
            if (row < BM) { src = pA; toff = 0;     r = row; }
            else          { src = pB; toff = DTILE; r = row - BM; }
            CP_ASYNC16(smem_u32(sb + toff + r * ROWB + seg * 16),
                       src + (size_t)r * C + k0 + seg * 8);
        }
        CP_COMMIT();
    };

    float acc[4][4][4];
#pragma unroll
    for (int mi = 0; mi < 4; mi++)
#pragma unroll
        for (int ni = 0; ni < 4; ni++)
#pragma unroll
            for (int j = 0; j < 4; j++) acc[mi][ni][j] = 0.f;

    const int NCH = C / KC;
    load_chunk(0, 0);
    load_chunk(1, KC);
    load_chunk(2, 2 * KC);
#pragma unroll 1
    for (int c = 0; c < NCH; c++) {
        if (c <= NCH - 3)      CP_WAIT2();
        else if (c == NCH - 2) CP_WAIT1();
        else                   CP_WAIT0();
        __syncthreads();
        if (c + 3 < NCH) load_chunk((c + 3) & 3, (c + 3) * KC);
        char* sb = smem + (c & 3) * DSTG;
        uint32_t aH = smem_u32(sb);
        uint32_t bH = aH + DTILE;
#pragma unroll
        for (int ks = 0; ks < 2; ks++) {
            uint32_t ah[4][4], bh[4][2];
            int acol = ks * 16 + (lane >> 4) * 8;
#pragma unroll
            for (int mi = 0; mi < 4; mi++) {
                uint32_t off = (uint32_t)((wm * 64 + mi * 16 + (lane & 15)) * ROWB + acol * 2);
                LDSM_X4(ah[mi], aH + off);
            }
            int l = lane & 15;
            int bcol = ks * 16 + (l >> 3) * 8;
#pragma unroll
            for (int ni = 0; ni < 4; ni++) {
                uint32_t off = (uint32_t)((wn * 32 + ni * 8 + (l & 7)) * ROWB + bcol * 2);
                LDSM_X2(bh[ni], bH + off);
            }
#pragma unroll
            for (int mi = 0; mi < 4; mi++)
#pragma unroll
                for (int ni = 0; ni < 4; ni++)
                    mma_f16(acc[mi][ni], ah[mi], bh[ni]);
        }
    }

    float* po = out + (size_t)z * C * HW;
#pragma unroll
    for (int mi = 0; mi < 4; mi++)
#pragma unroll
        for (int ni = 0; ni < 4; ni++) {
            int col = n0 + wn * 32 + ni * 8 + (lane & 3) * 2;
#pragma unroll
            for (int hrow = 0; hrow < 2; hrow++) {
                int r = m0 + wm * 64 + mi * 16 + (lane >> 2) + hrow * 8;
                float bm = bias[r];
                size_t off = (size_t)r * HW + col;
                float2 rx = *(const float2*)&resid[(size_t)z * C * HW + off];
                float2 v;
                v.x = acc[mi][ni][hrow * 2 + 0] + bm + rx.x;
                v.y = acc[mi][ni][hrow * 2 + 1] + bm + rx.y;
                *(float2*)&po[off] = v;
            }
        }
}

// =================== launch ===================================================
extern "C" void kernel_launch(void* const* d_in, const int* in_sizes, int n_in,
                              void* d_out, int out_size) {
    const float* x      = (const float*)d_in[0];
    const float* gn_w   = (const float*)d_in[1];
    const float* gn_b   = (const float*)d_in[2];
    const float* qkv_w  = (const float*)d_in[3];
    const float* qkv_b  = (const float*)d_in[4];
    const float* proj_w = (const float*)d_in[5];
    const float* proj_b = (const float*)d_in[6];
    float* out = (float*)d_out;

    static bool init = false;
    if (!init) {
        cudaFuncSetAttribute(qkv_gemm, cudaFuncAttributeMaxDynamicSharedMemorySize, SMQKV);
        cudaFuncSetAttribute(proj_gemm, cudaFuncAttributeMaxDynamicSharedMemorySize, SMPROJ);
        cudaFuncSetAttribute(flash_kernel, cudaFuncAttributeMaxDynamicSharedMemorySize, FL_SMEM);
        init = true;
    }

    prep_kernel<<<1280, 256>>>(x, qkv_w, proj_w);
    convT_kernel<<<dim3(HW / 32, C / 32, B), dim3(32, 8)>>>(x, gn_w, gn_b);

    qkv_gemm<<<dim3(HW / 128, 3 * C / 128, B), 256, SMQKV>>>(qkv_b);

    flash_kernel<<<dim3(HW / 64, B * HEADS), 256, FL_SMEM>>>();

    proj_gemm<<<dim3(HW / 128, C / 128, B), 256, SMPROJ>>>(proj_b, x, out);
}

// round 16
// speedup vs baseline: 1.1830x; 1.0321x over previous
#include <cuda_runtime.h>
#include <cuda_fp16.h>
#include <cstdint>
#include <math.h>

#define B    8
#define C    512
#define HW   1024
#define G    32
#define CPG  16
#define HEADS 8
#define DH   64
#define EPS  1e-5f
#define QSCALE 0.1803368867f   // 0.125 * log2(e)

// ---------------- scratch (device globals) ----------------------------------
__device__ float2 g_stats[B * G];

__device__ __half g_WhQ[3 * C * C];
__device__ __half g_WhP[C * C];
__device__ __half g_XTh [B * HW * C];          // [b][n][c]
__device__ __half g_AOTh[B * HW * C];          // [b][i][c]
__device__ __half g_qTh [B * HEADS * HW * DH]; // [bh][i][d] (log2-scaled)
__device__ __half g_kTh [B * HEADS * HW * DH]; // [bh][j][d]
__device__ __half g_Vh  [B * HEADS * DH * HW]; // [bh][d][j]

// =================== helpers ==================================================
__device__ __forceinline__ uint32_t smem_u32(const void* p) {
    uint32_t r;
    asm("{ .reg .u64 t; cvta.to.shared.u64 t, %1; cvt.u32.u64 %0, t; }"
        : "=r"(r) : "l"(p));
    return r;
}
#define CP_ASYNC16(dst, src) \
    asm volatile("cp.async.cg.shared.global [%0], [%1], 16;" :: "r"(dst), "l"(src) : "memory")
#define CP_COMMIT() asm volatile("cp.async.commit_group;" ::: "memory")
#define CP_WAIT1()  asm volatile("cp.async.wait_group 1;" ::: "memory")
#define CP_WAIT0()  asm volatile("cp.async.wait_group 0;" ::: "memory")
#define BAR_GROUP(id) asm volatile("bar.sync %0, %1;" :: "r"(id), "r"(128) : "memory")

#define LDSM_X4(r, addr) \
    asm volatile("ldmatrix.sync.aligned.m8n8.x4.shared.b16 {%0,%1,%2,%3}, [%4];" \
        : "=r"((r)[0]), "=r"((r)[1]), "=r"((r)[2]), "=r"((r)[3]) : "r"(addr))

__device__ __forceinline__ void mma_f16(float* c, const uint32_t* a, const uint32_t* b) {
    asm volatile(
        "mma.sync.aligned.m16n8k16.row.col.f32.f16.f16.f32 "
        "{%0,%1,%2,%3}, {%4,%5,%6,%7}, {%8,%9}, {%0,%1,%2,%3};"
        : "+f"(c[0]), "+f"(c[1]), "+f"(c[2]), "+f"(c[3])
        : "r"(a[0]), "r"(a[1]), "r"(a[2]), "r"(a[3]), "r"(b[0]), "r"(b[1]));
}
__device__ __forceinline__ void mma_h16(uint32_t* c, const uint32_t* a, const uint32_t* b) {
    asm volatile(
        "mma.sync.aligned.m16n8k16.row.col.f16.f16.f16.f16 "
        "{%0,%1}, {%2,%3,%4,%5}, {%6,%7}, {%0,%1};"
        : "+r"(c[0]), "+r"(c[1])
        : "r"(a[0]), "r"(a[1]), "r"(a[2]), "r"(a[3]), "r"(b[0]), "r"(b[1]));
}
__device__ __forceinline__ uint32_t packh(float x, float y) {
    __half2 h = __floats2half2_rn(x, y);
    return *(uint32_t*)&h;
}
__device__ __forceinline__ float ex2f(float x) {
    float y;
    asm("ex2.approx.f32 %0, %1;" : "=f"(y) : "f"(x));
    return y;
}
__device__ __forceinline__ uint32_t ex2h2(uint32_t x) {
    uint32_t y;
    asm("ex2.approx.f16x2 %0, %1;" : "=r"(y) : "r"(x));
    return y;
}
__device__ __forceinline__ uint32_t hmax2u(uint32_t a, uint32_t b) {
    __half2 r = __hmax2(*(__half2*)&a, *(__half2*)&b);
    return *(uint32_t*)&r;
}
__device__ __forceinline__ uint32_t hmul2u(uint32_t a, uint32_t b) {
    __half2 r = __hmul2(*(__half2*)&a, *(__half2*)&b);
    return *(uint32_t*)&r;
}
__device__ __forceinline__ uint32_t hsub2u(uint32_t a, uint32_t b) {
    __half2 r = __hsub2(*(__half2*)&a, *(__half2*)&b);
    return *(uint32_t*)&r;
}

// =========== fused prologue: gn stats + both weight converts ==================
__global__ __launch_bounds__(256) void prep_kernel(const float* __restrict__ x,
                                                   const float* __restrict__ qkv_w,
                                                   const float* __restrict__ proj_w) {
    int blk = blockIdx.x;
    if (blk < 256) {
        const float4* xp = (const float4*)(x + (size_t)blk * CPG * HW);
        const int N4 = CPG * HW / 4;
        float s = 0.f, s2 = 0.f;
        for (int i = threadIdx.x; i < N4; i += 256) {
            float4 v = xp[i];
            s  += v.x + v.y + v.z + v.w;
            s2 += v.x * v.x + v.y * v.y + v.z * v.z + v.w * v.w;
        }
        __shared__ float sh1[8], sh2[8];
        int lane = threadIdx.x & 31, wid = threadIdx.x >> 5;
        for (int o = 16; o; o >>= 1) {
            s  += __shfl_down_sync(0xffffffffu, s,  o);
            s2 += __shfl_down_sync(0xffffffffu, s2, o);
        }
        if (lane == 0) { sh1[wid] = s; sh2[wid] = s2; }
        __syncthreads();
        if (threadIdx.x == 0) {
            for (int i = 1; i < 8; i++) { sh1[0] += sh1[i]; sh2[0] += sh2[i]; }
            const float N = CPG * HW;
            float mean = sh1[0] * (1.f / N);
            float var  = sh2[0] * (1.f / N) - mean * mean;
            g_stats[blk] = make_float2(mean, rsqrtf(var + EPS));
        }
    } else if (blk < 1024) {
        int i = (blk - 256) * 1024 + threadIdx.x * 4;
        float4 v = *(const float4*)&qkv_w[i];
        *(uint32_t*)&g_WhQ[i]     = packh(v.x, v.y);
        *(uint32_t*)&g_WhQ[i + 2] = packh(v.z, v.w);
    } else {
        int i = (blk - 1024) * 1024 + threadIdx.x * 4;
        float4 v = *(const float4*)&proj_w[i];
        *(uint32_t*)&g_WhP[i]     = packh(v.x, v.y);
        *(uint32_t*)&g_WhP[i + 2] = packh(v.z, v.w);
    }
}

// ===== fused GN-apply + transpose + convert ===================================
__global__ __launch_bounds__(256) void convT_kernel(const float* __restrict__ x,
                                                    const float* __restrict__ gw,
                                                    const float* __restrict__ gb) {
    __shared__ float t[32][33];
    int n0 = blockIdx.x * 32, c0 = blockIdx.y * 32, b = blockIdx.z;
    const float* ip = x + (size_t)b * C * HW;
    int tx = threadIdx.x, ty = threadIdx.y;
#pragma unroll
    for (int k = 0; k < 4; k++) {
        int ch = c0 + ty + k * 8;
        float2 st = g_stats[b * G + (ch >> 4)];
        float v = ip[(size_t)ch * HW + n0 + tx];
        t[ty + k * 8][tx] = (v - st.x) * st.y * gw[ch] + gb[ch];
    }
    __syncthreads();
#pragma unroll
    for (int k = 0; k < 4; k++) {
        int ni = ty + k * 8;
        size_t o = (size_t)b * HW * C + (size_t)(n0 + ni) * C + c0 + tx;
        g_XTh[o] = __float2half(t[tx][ni]);
    }
}

// ============ dense GEMM config (KC=64, 3-stage dist-2, 2 CTA/SM) =============
#define KC     64
#define ROWB   144
#define DTILE  (128 * ROWB)             // 18432
#define DSTG   (2 * DTILE)              // 36864
#define SMDENSE (3 * DSTG)              // 110592
#define TSP    133

// =================== QKV GEMM =================================================
__global__ __launch_bounds__(256, 2) void qkv_gemm(const float* __restrict__ bias) {
    constexpr int BM = 128;
    extern __shared__ char smem[];

    const int tid = threadIdx.x;
    const int lane = tid & 31, wid = tid >> 5;
    const int wm = wid & 1, wn = wid >> 1;
    const int n0 = blockIdx.x * 128, m0 = blockIdx.y * 128;
    const int z = blockIdx.z;

    const __half* pA = g_WhQ + (size_t)m0 * C;
    const __half* pB = g_XTh + ((size_t)z * HW + n0) * C;

    auto load_chunk = [&](int stage, int k0) {
        char* sb = smem + stage * DSTG;
#pragma unroll
        for (int it = 0; it < 8; it++) {
            int idx = tid + it * 256;
            int row = idx >> 3, seg = idx & 7;
            const __half* src; int toff; int r;
            if (row < BM) { src = pA; toff = 0;     r = row; }
            else          { src = pB; toff = DTILE; r = row - BM; }
            CP_ASYNC16(smem_u32(sb + toff + r * ROWB + seg * 16),
                       src + (size_t)r * C + k0 + seg * 8);
        }
        CP_COMMIT();
    };

    float acc[4][4][4];
#pragma unroll
    for (int mi = 0; mi < 4; mi++)
#pragma unroll
        for (int ni = 0; ni < 4; ni++)
#pragma unroll
            for (int j = 0; j < 4; j++) acc[mi][ni][j] = 0.f;

    const int krow_l = ((lane >> 4) << 3) + (lane & 7);
    const int kcol_b = ((lane >> 3) & 1) * 8;

    const int NCH = C / KC;   // 8
    load_chunk(0, 0);
    load_chunk(1, KC);
#pragma unroll 1
    for (int c = 0; c < NCH; c++) {
        if (c + 1 < NCH) CP_WAIT1(); else CP_WAIT0();
        __syncthreads();
        if (c + 2 < NCH) load_chunk((c + 2) % 3, (c + 2) * KC);
        char* sb = smem + (c % 3) * DSTG;
        uint32_t aH = smem_u32(sb);
        uint32_t bH = aH + DTILE;
#pragma unroll
        for (int ks = 0; ks < 4; ks++) {
            uint32_t ah[4][4], bp[2][4];
            int acol = ks * 16 + (lane >> 4) * 8;
#pragma unroll
            for (int mi = 0; mi < 4; mi++) {
                uint32_t off = (uint32_t)((wm * 64 + mi * 16 + (lane & 15)) * ROWB + acol * 2);
                LDSM_X4(ah[mi], aH + off);
            }
            int kcol = ks * 16 + kcol_b;
#pragma unroll
            for (int np = 0; np < 2; np++) {
                uint32_t off = (uint32_t)((wn * 32 + np * 16 + krow_l) * ROWB + kcol * 2);
                LDSM_X4(bp[np], bH + off);
            }
#pragma unroll
            for (int mi = 0; mi < 4; mi++)
#pragma unroll
                for (int np = 0; np < 2; np++) {
                    mma_f16(acc[mi][2 * np],     ah[mi], bp[np]);
                    mma_f16(acc[mi][2 * np + 1], ah[mi], bp[np] + 2);
                }
        }
    }

    const int sec = m0 >> 9;
    const float scale = (sec == 0) ? QSCALE : 1.0f;

    __syncthreads();
    float* ts = (float*)smem;
    if (sec == 2) {
#pragma unroll
        for (int mi = 0; mi < 4; mi++)
#pragma unroll
            for (int ni = 0; ni < 4; ni++) {
                int col = wn * 32 + ni * 8 + (lane & 3) * 2;
#pragma unroll
                for (int hrow = 0; hrow < 2; hrow++) {
                    int r = wm * 64 + mi * 16 + (lane >> 2) + hrow * 8;
                    float bm = bias[m0 + r];
                    ts[r * TSP + col]     = acc[mi][ni][hrow * 2 + 0] + bm;
                    ts[r * TSP + col + 1] = acc[mi][ni][hrow * 2 + 1] + bm;
                }
            }
        __syncthreads();
#pragma unroll
        for (int it = 0; it < 32; it++) {
            int e = tid + it * 256;
            int j2 = e & 63;
            int row = e >> 6;
            float a  = ts[row * TSP + j2 * 2];
            float bb = ts[row * TSP + j2 * 2 + 1];
            int mC = (m0 - 1024) + row;
            size_t o = ((size_t)(z * HEADS + (mC >> 6)) * DH + (mC & 63)) * HW + n0 + j2 * 2;
            *(uint32_t*)&g_Vh[o] = packh(a, bb);
        }
    } else {
#pragma unroll
        for (int mi = 0; mi < 4; mi++)
#pragma unroll
            for (int ni = 0; ni < 4; ni++) {
                int col = wn * 32 + ni * 8 + (lane & 3) * 2;
#pragma unroll
                for (int hrow = 0; hrow < 2; hrow++) {
                    int r = wm * 64 + mi * 16 + (lane >> 2) + hrow * 8;
                    float bm = bias[m0 + r];
                    ts[r * TSP + col]     = (acc[mi][ni][hrow * 2 + 0] + bm) * scale;
                    ts[r * TSP + col + 1] = (acc[mi][ni][hrow * 2 + 1] + bm) * scale;
                }
            }
        __syncthreads();
        __half* oh = sec ? g_kTh : g_qTh;
        int h0 = (m0 & 511) >> 6;
#pragma unroll
        for (int it = 0; it < 32; it++) {
            int e = tid + it * 256;
            int dp = e & 31;
            int i  = (e >> 5) & 127;
            int hh = e >> 12;
            float a  = ts[(hh * 64 + dp * 2)     * TSP + i];
            float bb = ts[(hh * 64 + dp * 2 + 1) * TSP + i];
            size_t o = ((size_t)(z * HEADS + h0 + hh) * HW + n0 + i) * DH + dp * 2;
            *(uint32_t*)&oh[o] = packh(a, bb);
        }
    }
}

// =================== flash attention (f16 accumulators) =======================
#define QROWB   144
#define VROWB   272
#define FQ_TILE 9216
#define FK_TILE 18432
#define FV_TILE 17408
#define FL_STAGEB (FK_TILE + FV_TILE)
#define FL_SMEM (FQ_TILE + 2 * FL_STAGEB) // 80896

__global__ __launch_bounds__(256, 2) void flash_kernel() {
    extern __shared__ char smem[];
    const int tid = threadIdx.x, lane = tid & 31, wid = tid >> 5;
    const int wm = wid & 3;
    const int jw = wid >> 2;
    const int gtid = tid & 127;
    const int barid = 1 + jw;
    const int i0 = blockIdx.x * 64;
    const int bh = blockIdx.y;
    const int b = bh >> 3, h = bh & 7;
    const int wr = wm * 16;
    const uint32_t ONES2[2] = {0x3C003C00u, 0x3C003C00u};

    auto ld_Q = [&]() {
#pragma unroll
        for (int it = 0; it < 2; it++) {
            int idx = tid + it * 256;
            int r = idx >> 3, seg = idx & 7;
            const __half* src = g_qTh + ((size_t)bh * HW + i0 + r) * DH + seg * 8;
            CP_ASYNC16(smem_u32(smem + r * QROWB + seg * 16), src);
        }
    };
    auto ld_KV = [&](int jt, int st) {
        char* sb = smem + FQ_TILE + st * FL_STAGEB;
        int j0 = jt * 128;
#pragma unroll
        for (int it = 0; it < 4; it++) {
            int idx = gtid + it * 128;
            int r = jw * 64 + (idx >> 3), seg = idx & 7;
            const __half* src = g_kTh + ((size_t)bh * HW + j0 + r) * DH + seg * 8;
            CP_ASYNC16(smem_u32(sb + r * QROWB + seg * 16), src);
        }
#pragma unroll
        for (int it = 0; it < 4; it++) {
            int idx = gtid + it * 128;
            int r = idx >> 3, seg = jw * 8 + (idx & 7);
            const __half* src = g_Vh + ((size_t)bh * DH + r) * HW + j0 + seg * 8;
            CP_ASYNC16(smem_u32(sb + FK_TILE + r * VROWB + seg * 16), src);
        }
        CP_COMMIT();
    };

    uint32_t acc_o[8][2];
#pragma unroll
    for (int dt = 0; dt < 8; dt++) { acc_o[dt][0] = 0u; acc_o[dt][1] = 0u; }
    uint32_t lacc[2] = {0u, 0u};
    float mrow0 = -INFINITY, mrow1 = -INFINITY;

    const uint32_t qH = smem_u32(smem);

    ld_Q(); ld_KV(0, 0); CP_COMMIT();
    ld_KV(1, 1);
    CP_WAIT1();
    __syncthreads();

    uint32_t qa[4][4];
#pragma unroll
    for (int ks = 0; ks < 4; ks++) {
        uint32_t aoff = (uint32_t)((wr + (lane & 15)) * QROWB +
                                   (ks * 16 + (lane >> 4) * 8) * 2);
        LDSM_X4(qa[ks], qH + aoff);
    }

    const int krow_l = ((lane >> 4) << 3) + (lane & 7);
    const int kcol_b = ((lane >> 3) & 1) * 8;

#pragma unroll 1
    for (int jt = 0; jt < 8; jt++) {
        uint32_t kb = smem_u32(smem + FQ_TILE + (jt & 1) * FL_STAGEB);
        uint32_t kH = kb;
        uint32_t vH = kb + FK_TILE;

        uint32_t s[8][2];
#pragma unroll
        for (int nt = 0; nt < 8; nt++) { s[nt][0] = 0u; s[nt][1] = 0u; }

#pragma unroll
        for (int ks = 0; ks < 4; ks++) {
            int kcol = ks * 16 + kcol_b;
#pragma unroll
            for (int ntp = 0; ntp < 4; ntp++) {
                uint32_t bh_[4];
                uint32_t boff = (uint32_t)((jw * 64 + ntp * 16 + krow_l) * QROWB + kcol * 2);
                LDSM_X4(bh_, kH + boff);
                mma_h16(s[2 * ntp],     qa[ks], bh_);
                mma_h16(s[2 * ntp + 1], qa[ks], bh_ + 2);
            }
        }

        uint32_t m0p = s[0][0], m1p = s[0][1];
#pragma unroll
        for (int nt = 1; nt < 8; nt++) {
            m0p = hmax2u(m0p, s[nt][0]);
            m1p = hmax2u(m1p, s[nt][1]);
        }
        m0p = hmax2u(m0p, __shfl_xor_sync(0xffffffffu, m0p, 1));
        m0p = hmax2u(m0p, __shfl_xor_sync(0xffffffffu, m0p, 2));
        m1p = hmax2u(m1p, __shfl_xor_sync(0xffffffffu, m1p, 1));
        m1p = hmax2u(m1p, __shfl_xor_sync(0xffffffffu, m1p, 2));
        __half2 m0h = *(__half2*)&m0p, m1h = *(__half2*)&m1p;
        float mx0 = __half2float(__hmax(__low2half(m0h), __high2half(m0h)));
        float mx1 = __half2float(__hmax(__low2half(m1h), __high2half(m1h)));
        float mn0 = fmaxf(mrow0, mx0), mn1 = fmaxf(mrow1, mx1);
        float al0 = ex2f(mrow0 - mn0), al1 = ex2f(mrow1 - mn1);
        mrow0 = mn0; mrow1 = mn1;
        uint32_t al02 = packh(al0, al0), al12 = packh(al1, al1);
#pragma unroll
        for (int dt = 0; dt < 8; dt++) {
            acc_o[dt][0] = hmul2u(acc_o[dt][0], al02);
            acc_o[dt][1] = hmul2u(acc_o[dt][1], al12);
        }
        lacc[0] = hmul2u(lacc[0], al02);
        lacc[1] = hmul2u(lacc[1], al12);

        uint32_t mn02 = packh(mn0, mn0), mn12 = packh(mn1, mn1);
#pragma unroll
        for (int nt = 0; nt < 8; nt++) {
            s[nt][0] = ex2h2(hsub2u(s[nt][0], mn02));
            s[nt][1] = ex2h2(hsub2u(s[nt][1], mn12));
        }

#pragma unroll
        for (int kk = 0; kk < 4; kk++) {
            uint32_t aph[4];
            aph[0] = s[2 * kk][0];     aph[1] = s[2 * kk][1];
            aph[2] = s[2 * kk + 1][0]; aph[3] = s[2 * kk + 1][1];
            mma_h16(lacc, aph, ONES2);
            int vcol = jw * 64 + kk * 16 + kcol_b;
#pragma unroll
            for (int dt = 0; dt < 4; dt++) {
                uint32_t bvh[4];
                uint32_t off = (uint32_t)((dt * 16 + krow_l) * VROWB + vcol * 2);
                LDSM_X4(bvh, vH + off);
                mma_h16(acc_o[2 * dt],     aph, bvh);
                mma_h16(acc_o[2 * dt + 1], aph, bvh + 2);
            }
        }

        BAR_GROUP(barid);
        if (jt + 2 < 8)      { ld_KV(jt + 2, jt & 1); CP_WAIT1(); }
        else if (jt + 1 < 8) { CP_WAIT0(); }
        BAR_GROUP(barid);
    }

    float lrow0 = __half2float(__low2half(*(__half2*)&lacc[0]));
    float lrow1 = __half2float(__low2half(*(__half2*)&lacc[1]));

    float ao[8][4];
#pragma unroll
    for (int dt = 0; dt < 8; dt++) {
        float2 lo = __half22float2(*(__half2*)&acc_o[dt][0]);
        float2 hi = __half22float2(*(__half2*)&acc_o[dt][1]);
        ao[dt][0] = lo.x; ao[dt][1] = lo.y;
        ao[dt][2] = hi.x; ao[dt][3] = hi.y;
    }

    __syncthreads();
    float* mo = (float*)smem;
    float* ml = (float*)(smem + 64 * 68 * 4);
    float* ll = ml + 64;
    int r0 = wr + (lane >> 2);
    int cb = (lane & 3) * 2;

    if (jw == 1) {
#pragma unroll
        for (int dt = 0; dt < 8; dt++) {
            mo[r0 * 68 + dt * 8 + cb]           = ao[dt][0];
            mo[r0 * 68 + dt * 8 + cb + 1]       = ao[dt][1];
            mo[(r0 + 8) * 68 + dt * 8 + cb]     = ao[dt][2];
            mo[(r0 + 8) * 68 + dt * 8 + cb + 1] = ao[dt][3];
        }
        if ((lane & 3) == 0) {
            ml[r0] = mrow0; ml[r0 + 8] = mrow1;
            ll[r0] = lrow0; ll[r0 + 8] = lrow1;
        }
    }
    __syncthreads();
    if (jw == 0) {
        float mB0 = ml[r0],     lB0 = ll[r0];
        float mB1 = ml[r0 + 8], lB1 = ll[r0 + 8];
        float m0 = fmaxf(mrow0, mB0), m1 = fmaxf(mrow1, mB1);
        float a0 = ex2f(mrow0 - m0), b0 = ex2f(mB0 - m0);
        float a1 = ex2f(mrow1 - m1), b1 = ex2f(mB1 - m1);
        float inv0 = 1.f / (lrow0 * a0 + lB0 * b0);
        float inv1 = 1.f / (lrow1 * a1 + lB1 * b1);
        int cbase = h * DH + cb;
#pragma unroll
        for (int dt = 0; dt < 8; dt++) {
            float ox = (ao[dt][0] * a0 + mo[r0 * 68 + dt * 8 + cb]     * b0) * inv0;
            float oy = (ao[dt][1] * a0 + mo[r0 * 68 + dt * 8 + cb + 1] * b0) * inv0;
            size_t o0 = ((size_t)b * HW + i0 + r0) * C + cbase + dt * 8;
            *(uint32_t*)&g_AOTh[o0] = packh(ox, oy);
            ox = (ao[dt][2] * a1 + mo[(r0 + 8) * 68 + dt * 8 + cb]     * b1) * inv1;
            oy = (ao[dt][3] * a1 + mo[(r0 + 8) * 68 + dt * 8 + cb + 1] * b1) * inv1;
            size_t o1 = ((size_t)b * HW + i0 + r0 + 8) * C + cbase + dt * 8;
            *(uint32_t*)&g_AOTh[o1] = packh(ox, oy);
        }
    }
}

// =================== proj GEMM ================================================
__global__ __launch_bounds__(256, 2) void proj_gemm(const float* __restrict__ bias,
                                                    const float* __restrict__ resid,
                                                    float* __restrict__ out) {
    constexpr int BM = 128;
    extern __shared__ char smem[];

    const int tid = threadIdx.x;
    const int lane = tid & 31, wid = tid >> 5;
    const int wm = wid & 1, wn = wid >> 1;
    const int n0 = blockIdx.x * 128, m0 = blockIdx.y * 128;
    const int z = blockIdx.z;

    const __half* pA = g_WhP + (size_t)m0 * C;
    const __half* pB = g_AOTh + ((size_t)z * HW + n0) * C;

    auto load_chunk = [&](int stage, int k0) {
        char* sb = smem + stage * DSTG;
#pragma unroll
        for (int it = 0; it < 8; it++) {
            int idx = tid + it * 256;
            int row = idx >> 3, seg = idx & 7;
            const __half* src; int toff; int r;
            if (row < BM) { src = pA; toff = 0;     r = row; }
            else          { src = pB; toff = DTILE; r = row - BM; }
            CP_ASYNC16(smem_u32(sb + toff + r * ROWB + seg * 16),
                       src + (size_t)r * C + k0 + seg * 8);
        }
        CP_COMMIT();
    };

    float acc[4][4][4];
#pragma unroll
    for (int mi = 0; mi < 4; mi++)
#pragma unroll
        for (int ni = 0; ni < 4; ni++)
#pragma unroll
            for (int j = 0; j < 4; j++) acc[mi][ni][j] = 0.f;

    const int krow_l = ((lane >> 4) << 3) + (lane & 7);
    const int kcol_b = ((lane >> 3) & 1) * 8;

    const int NCH = C / KC;
    load_chunk(0, 0);
    load_chunk(1, KC);
#pragma unroll 1
    for (int c = 0; c < NCH; c++) {
        if (c + 1 < NCH) CP_WAIT1(); else CP_WAIT0();
        __syncthreads();
        if (c + 2 < NCH) load_chunk((c + 2) % 3, (c + 2) * KC);
        char* sb = smem + (c % 3) * DSTG;
        uint32_t aH = smem_u32(sb);
        uint32_t bH = aH + DTILE;
#pragma unroll
        for (int ks = 0; ks < 4; ks++) {
            uint32_t ah[4][4], bp[2][4];
            int acol = ks * 16 + (lane >> 4) * 8;
#pragma unroll
            for (int mi = 0; mi < 4; mi++) {
                uint32_t off = (uint32_t)((wm * 64 + mi * 16 + (lane & 15)) * ROWB + acol * 2);
                LDSM_X4(ah[mi], aH + off);
            }
            int kcol = ks * 16 + kcol_b;
#pragma unroll
            for (int np = 0; np < 2; np++) {
                uint32_t off = (uint32_t)((wn * 32 + np * 16 + krow_l) * ROWB + kcol * 2);
                LDSM_X4(bp[np], bH + off);
            }
#pragma unroll
            for (int mi = 0; mi < 4; mi++)
#pragma unroll
                for (int np = 0; np < 2; np++) {
                    mma_f16(acc[mi][2 * np],     ah[mi], bp[np]);
                    mma_f16(acc[mi][2 * np + 1], ah[mi], bp[np] + 2);
                }
        }
    }

    float* po = out + (size_t)z * C * HW;
#pragma unroll
    for (int mi = 0; mi < 4; mi++)
#pragma unroll
        for (int ni = 0; ni < 4; ni++) {
            int col = n0 + wn * 32 + ni * 8 + (lane & 3) * 2;
#pragma unroll
            for (int hrow = 0; hrow < 2; hrow++) {
                int r = m0 + wm * 64 + mi * 16 + (lane >> 2) + hrow * 8;
                float bm = bias[r];
                size_t off = (size_t)r * HW + col;
                float2 rx = *(const float2*)&resid[(size_t)z * C * HW + off];
                float2 v;
                v.x = acc[mi][ni][hrow * 2 + 0] + bm + rx.x;
                v.y = acc[mi][ni][hrow * 2 + 1] + bm + rx.y;
                *(float2*)&po[off] = v;
            }
        }
}

// =================== launch ===================================================
extern "C" void kernel_launch(void* const* d_in, const int* in_sizes, int n_in,
                              void* d_out, int out_size) {
    const float* x      = (const float*)d_in[0];
    const float* gn_w   = (const float*)d_in[1];
    const float* gn_b   = (const float*)d_in[2];
    const float* qkv_w  = (const float*)d_in[3];
    const float* qkv_b  = (const float*)d_in[4];
    const float* proj_w = (const float*)d_in[5];
    const float* proj_b = (const float*)d_in[6];
    float* out = (float*)d_out;

    static bool init = false;
    if (!init) {
        cudaFuncSetAttribute(qkv_gemm, cudaFuncAttributeMaxDynamicSharedMemorySize, SMDENSE);
        cudaFuncSetAttribute(proj_gemm, cudaFuncAttributeMaxDynamicSharedMemorySize, SMDENSE);
        cudaFuncSetAttribute(flash_kernel, cudaFuncAttributeMaxDynamicSharedMemorySize, FL_SMEM);
        init = true;
    }

    prep_kernel<<<1280, 256>>>(x, qkv_w, proj_w);
    convT_kernel<<<dim3(HW / 32, C / 32, B), dim3(32, 8)>>>(x, gn_w, gn_b);

    qkv_gemm<<<dim3(HW / 128, 3 * C / 128, B), 256, SMDENSE>>>(qkv_b);

    flash_kernel<<<dim3(HW / 64, B * HEADS), 256, FL_SMEM>>>();

    proj_gemm<<<dim3(HW / 128, C / 128, B), 256, SMDENSE>>>(proj_b, x, out);
}